// round 16
// baseline (speedup 1.0000x reference)
#include <cuda_runtime.h>
#include <stdint.h>

#define MM    16
#define DIMK  64
#define STR   68            // padded shared row stride (floats)
#define GPB   4             // groups (warps) per block
#define EPSV  0.006f
#define MAXG  8192
#define MAXBLK (MAXG / GPB)

// log2(e)/64 : exp(-ws*d/64) == ex2(-(ws*log2e/64)*d)
#define L2E_OVER_D 0.02254211001444292f

__device__ float        g_blocksum[MAXBLK];
__device__ unsigned int g_count = 0;

union F4 {
    float4 v;
    unsigned long long u[2];
    float f[4];
};

// packed dual-FMA (Blackwell FFMA2)
__device__ __forceinline__ unsigned long long ffma2(unsigned long long a,
                                                    unsigned long long b,
                                                    unsigned long long c) {
    unsigned long long d;
    asm("fma.rn.f32x2 %0, %1, %2, %3;" : "=l"(d) : "l"(a), "l"(b), "l"(c));
    return d;
}

__device__ __forceinline__ float hsum2(unsigned long long u) {
    float lo, hi;
    asm("mov.b64 {%0, %1}, %2;" : "=f"(lo), "=f"(hi) : "l"(u));
    return lo + hi;
}

// MUFU.SQRT / MUFU.EX2 — idle pipe; accuracy ~2^-22, far inside 1e-3 budget
__device__ __forceinline__ float mufu_sqrt(float x) {
    float r;
    asm("sqrt.approx.f32 %0, %1;" : "=f"(r) : "f"(x));
    return r;
}
__device__ __forceinline__ float mufu_ex2(float x) {
    float r;
    asm("ex2.approx.f32 %0, %1;" : "=f"(r) : "f"(x));
    return r;
}

// async 16B global->shared copy (LDGSTS)
__device__ __forceinline__ void cp16(uint32_t dst_smem, const void* src) {
    asm volatile("cp.async.cg.shared.global [%0], [%1], 16;"
                 :: "r"(dst_smem), "l"(src) : "memory");
}
__device__ __forceinline__ void cp_commit_wait() {
    asm volatile("cp.async.commit_group;" ::: "memory");
    asm volatile("cp.async.wait_group 0;" ::: "memory");
}

// min-blocks=6: cap regs at 85 -> 6 blocks/SM, 24 warps. Single-variable
// experiment vs R15 (which was (.,5)/96 regs @ 33.5us). Body shrank since R4's
// failed 80-cap (norm pass eliminated), so -11 regs is a mild squeeze.
__global__ void __launch_bounds__(GPB * 32, 6)
imm_fused_kernel(const float* __restrict__ xs,   // ys_t      [G,16,64]
                 const float* __restrict__ ysr,  // ys_r_stop [G,16,64]
                 const float* __restrict__ wsc,  // w_scale [B]
                 const float* __restrict__ twg,  // time_weights [B]
                 float* __restrict__ out,
                 int G)
{
    __shared__ float shx[GPB][MM * STR];
    __shared__ float shy[GPB][MM * STR];
    __shared__ float shn[GPB][32];      // [0:16)=|x_i|^2, [16:32)=|y_i|^2
    __shared__ float s_part[GPB];
    __shared__ int   s_last;

    const int warp = threadIdx.x >> 5;
    const int lane = threadIdx.x & 31;
    const int g = blockIdx.x * GPB + warp;
    const bool valid = (g < G);

    float* X = shx[warp];
    float* Y = shy[warp];

    // ---- stage group tiles (16x64 each) into padded shared via cp.async ----
    if (valid) {
        const float4* gx = (const float4*)(xs  + (size_t)g * (MM * DIMK));
        const float4* gy = (const float4*)(ysr + (size_t)g * (MM * DIMK));
        const uint32_t xb = (uint32_t)__cvta_generic_to_shared(X);
        const uint32_t yb = (uint32_t)__cvta_generic_to_shared(Y);
#pragma unroll
        for (int t = lane; t < MM * DIMK / 4; t += 32) {
            int row = t >> 4;          // 16 float4 per row
            int c4  = t & 15;
            uint32_t off = (uint32_t)(row * STR + c4 * 4) * 4u;
            cp16(xb + off, gx + t);
            cp16(yb + off, gy + t);
        }
    }
    cp_commit_wait();
    __syncwarp();

    float lsum = 0.f;

    if (valid) {
        // ---- three 16x16 Gram matrices via packed f32x2 FMA ----
        // lane owns i in {a, a+8}, j in {b, b+4, b+8, b+12}
        const int a = lane >> 2;
        const int b = lane & 3;

        unsigned long long Gxx[2][4], Gyy[2][4], Gxy[2][4];
#pragma unroll
        for (int p = 0; p < 2; p++)
#pragma unroll
            for (int c = 0; c < 4; c++) {
                Gxx[p][c] = 0ull; Gyy[p][c] = 0ull; Gxy[p][c] = 0ull;
            }

        const float* xa0p = X + a * STR;
        const float* xa1p = X + (a + 8) * STR;
        const float* ya0p = Y + a * STR;
        const float* ya1p = Y + (a + 8) * STR;

#pragma unroll 4
        for (int kk = 0; kk < DIMK / 4; kk++) {
            const int k = kk * 4;
            F4 xa0, xa1, ya0, ya1;
            xa0.v = *(const float4*)(xa0p + k);
            xa1.v = *(const float4*)(xa1p + k);
            ya0.v = *(const float4*)(ya0p + k);
            ya1.v = *(const float4*)(ya1p + k);
#pragma unroll
            for (int c = 0; c < 4; c++) {
                F4 xbv, ybv;
                xbv.v = *(const float4*)(X + (b + 4 * c) * STR + k);
                ybv.v = *(const float4*)(Y + (b + 4 * c) * STR + k);

                Gxx[0][c] = ffma2(xa0.u[0], xbv.u[0], Gxx[0][c]);
                Gxx[0][c] = ffma2(xa0.u[1], xbv.u[1], Gxx[0][c]);
                Gxx[1][c] = ffma2(xa1.u[0], xbv.u[0], Gxx[1][c]);
                Gxx[1][c] = ffma2(xa1.u[1], xbv.u[1], Gxx[1][c]);

                Gyy[0][c] = ffma2(ya0.u[0], ybv.u[0], Gyy[0][c]);
                Gyy[0][c] = ffma2(ya0.u[1], ybv.u[1], Gyy[0][c]);
                Gyy[1][c] = ffma2(ya1.u[0], ybv.u[0], Gyy[1][c]);
                Gyy[1][c] = ffma2(ya1.u[1], ybv.u[1], Gyy[1][c]);

                Gxy[0][c] = ffma2(xa0.u[0], ybv.u[0], Gxy[0][c]);
                Gxy[0][c] = ffma2(xa0.u[1], ybv.u[1], Gxy[0][c]);
                Gxy[1][c] = ffma2(xa1.u[0], ybv.u[0], Gxy[1][c]);
                Gxy[1][c] = ffma2(xa1.u[1], ybv.u[1], Gxy[1][c]);
            }
        }

        // ---- norms from the Gram diagonal (free): Gxx[i][i] = |x_i|^2 ----
        // Lane owns (i,i) iff b == (a&3): p=0 diag at c = a>>2, p=1 at c = (a>>2)+2.
        // Accumulation order identical to a dedicated norm pass -> bit-identical.
        if (b == (a & 3)) {
            const int hi = a >> 2;     // 0 or 1
            unsigned long long gx0 = hi ? Gxx[0][1] : Gxx[0][0];
            unsigned long long gy0 = hi ? Gyy[0][1] : Gyy[0][0];
            unsigned long long gx1 = hi ? Gxx[1][3] : Gxx[1][2];
            unsigned long long gy1 = hi ? Gyy[1][3] : Gyy[1][2];
            shn[warp][a]          = hsum2(gx0);
            shn[warp][16 + a]     = hsum2(gy0);
            shn[warp][a + 8]      = hsum2(gx1);
            shn[warp][16 + a + 8] = hsum2(gy1);
        }
        __syncwarp();

        // ---- epilogue: d^2 = n_i + n_j - 2 g_ij, clamp, MUFU sqrt + ex2 ----
        const float* nrm = shn[warp];
        const float nxa0 = nrm[a],      nxa1 = nrm[a + 8];
        const float nya0 = nrm[16 + a], nya1 = nrm[16 + a + 8];
        const float wl0 = -wsc[g * MM + a]     * L2E_OVER_D;
        const float wl1 = -wsc[g * MM + a + 8] * L2E_OVER_D;

#pragma unroll
        for (int c = 0; c < 4; c++) {
            const int j = b + 4 * c;
            const float nxj = nrm[j];
            const float nyj = nrm[16 + j];

            float d0 = fmaxf(fmaf(-2.f, hsum2(Gxx[0][c]), nxa0 + nxj), EPSV * EPSV);
            float d1 = fmaxf(fmaf(-2.f, hsum2(Gyy[0][c]), nya0 + nyj), EPSV * EPSV);
            float d2 = fmaxf(fmaf(-2.f, hsum2(Gxy[0][c]), nxa0 + nyj), EPSV * EPSV);
            float d3 = fmaxf(fmaf(-2.f, hsum2(Gxx[1][c]), nxa1 + nxj), EPSV * EPSV);
            float d4 = fmaxf(fmaf(-2.f, hsum2(Gyy[1][c]), nya1 + nyj), EPSV * EPSV);
            float d5 = fmaxf(fmaf(-2.f, hsum2(Gxy[1][c]), nxa1 + nyj), EPSV * EPSV);

            float t0 = mufu_ex2(wl0 * mufu_sqrt(d0));
            float t1 = mufu_ex2(wl0 * mufu_sqrt(d1));
            float t2 = mufu_ex2(wl0 * mufu_sqrt(d2));
            float t3 = mufu_ex2(wl1 * mufu_sqrt(d3));
            float t4 = mufu_ex2(wl1 * mufu_sqrt(d4));
            float t5 = mufu_ex2(wl1 * mufu_sqrt(d5));
            lsum += (t0 + t1 - 2.f * t2) + (t3 + t4 - 2.f * t5);
        }

        // warp reduction -> per-group value (deterministic)
#pragma unroll
        for (int off = 16; off; off >>= 1)
            lsum += __shfl_xor_sync(0xffffffffu, lsum, off);
    }

    if (lane == 0)
        s_part[warp] = valid ? lsum * twg[g * MM] * (1.0f / (float)(MM * MM)) : 0.f;
    __syncthreads();

    // ---- block partial + last-block-done grid reduction ----
    if (threadIdx.x == 0) {
        float bs = 0.f;
#pragma unroll
        for (int w = 0; w < GPB; w++) bs += s_part[w];
        g_blocksum[blockIdx.x] = bs;
        __threadfence();
        unsigned int v = atomicAdd(&g_count, 1u);
        s_last = (v == gridDim.x - 1u) ? 1 : 0;
    }
    __syncthreads();

    if (s_last) {
        const int nb = gridDim.x;
        float acc = 0.f;
        for (int i = threadIdx.x; i < nb; i += GPB * 32)
            acc += g_blocksum[i];
#pragma unroll
        for (int off = 16; off; off >>= 1)
            acc += __shfl_xor_sync(0xffffffffu, acc, off);
        if (lane == 0) s_part[warp] = acc;
        __syncthreads();
        if (threadIdx.x == 0) {
            float tot = 0.f;
#pragma unroll
            for (int w = 0; w < GPB; w++) tot += s_part[w];
            out[0] = tot / (float)G;
            g_count = 0;   // reset for next graph replay
        }
    }
}

extern "C" void kernel_launch(void* const* d_in, const int* in_sizes, int n_in,
                              void* d_out, int out_size)
{
    const float* xs  = (const float*)d_in[0];   // ys_t
    const float* ysr = (const float*)d_in[1];   // ys_r_stop
    const float* ws  = (const float*)d_in[2];   // w_scale
    const float* tw  = (const float*)d_in[3];   // time_weights

    const int n = in_sizes[0];          // B * 16 * 4
    const int B = n / DIMK;
    int G = B / MM;
    if (G > MAXG) G = MAXG;

    const int blocks = (G + GPB - 1) / GPB;
    imm_fused_kernel<<<blocks, GPB * 32>>>(xs, ysr, ws, tw, (float*)d_out, G);
}

// round 17
// speedup vs baseline: 1.1220x; 1.1220x over previous
#include <cuda_runtime.h>
#include <stdint.h>

#define MM    16
#define DIMK  64
#define STR   68            // padded shared row stride (floats)
#define GPB   4             // groups (warps) per block
#define EPSV  0.006f
#define MAXG  8192
#define MAXBLK (MAXG / GPB)

// log2(e)/64 : exp(-ws*d/64) == ex2(-(ws*log2e/64)*d)
#define L2E_OVER_D 0.02254211001444292f

__device__ float        g_blocksum[MAXBLK];
__device__ unsigned int g_count = 0;

union F4 {
    float4 v;
    unsigned long long u[2];
    float f[4];
};

// packed dual-FMA (Blackwell FFMA2)
__device__ __forceinline__ unsigned long long ffma2(unsigned long long a,
                                                    unsigned long long b,
                                                    unsigned long long c) {
    unsigned long long d;
    asm("fma.rn.f32x2 %0, %1, %2, %3;" : "=l"(d) : "l"(a), "l"(b), "l"(c));
    return d;
}

__device__ __forceinline__ float hsum2(unsigned long long u) {
    float lo, hi;
    asm("mov.b64 {%0, %1}, %2;" : "=f"(lo), "=f"(hi) : "l"(u));
    return lo + hi;
}

// MUFU.SQRT / MUFU.EX2 — idle pipe; accuracy ~2^-22, far inside 1e-3 budget
__device__ __forceinline__ float mufu_sqrt(float x) {
    float r;
    asm("sqrt.approx.f32 %0, %1;" : "=f"(r) : "f"(x));
    return r;
}
__device__ __forceinline__ float mufu_ex2(float x) {
    float r;
    asm("ex2.approx.f32 %0, %1;" : "=f"(r) : "f"(x));
    return r;
}

// async 16B global->shared copy (LDGSTS)
__device__ __forceinline__ void cp16(uint32_t dst_smem, const void* src) {
    asm volatile("cp.async.cg.shared.global [%0], [%1], 16;"
                 :: "r"(dst_smem), "l"(src) : "memory");
}
__device__ __forceinline__ void cp_commit_wait() {
    asm volatile("cp.async.commit_group;" ::: "memory");
    asm volatile("cp.async.wait_group 0;" ::: "memory");
}

// min-blocks=5 (PROVEN: R15 @33.5us, regs 96). min-blocks=6 regressed (R16:
// forced 80 regs -> alu-pipe recompute spills, 35.3us). Do not re-try 6.
__global__ void __launch_bounds__(GPB * 32, 5)
imm_fused_kernel(const float* __restrict__ xs,   // ys_t      [G,16,64]
                 const float* __restrict__ ysr,  // ys_r_stop [G,16,64]
                 const float* __restrict__ wsc,  // w_scale [B]
                 const float* __restrict__ twg,  // time_weights [B]
                 float* __restrict__ out,
                 int G)
{
    __shared__ float shx[GPB][MM * STR];
    __shared__ float shy[GPB][MM * STR];
    __shared__ float shn[GPB][32];      // [0:16)=|x_i|^2, [16:32)=|y_i|^2
    __shared__ float s_part[GPB];
    __shared__ int   s_last;

    const int warp = threadIdx.x >> 5;
    const int lane = threadIdx.x & 31;
    const int g = blockIdx.x * GPB + warp;
    const bool valid = (g < G);

    float* X = shx[warp];
    float* Y = shy[warp];

    // ---- stage group tiles (16x64 each) into padded shared via cp.async ----
    if (valid) {
        const float4* gx = (const float4*)(xs  + (size_t)g * (MM * DIMK));
        const float4* gy = (const float4*)(ysr + (size_t)g * (MM * DIMK));
        const uint32_t xb = (uint32_t)__cvta_generic_to_shared(X);
        const uint32_t yb = (uint32_t)__cvta_generic_to_shared(Y);
#pragma unroll
        for (int t = lane; t < MM * DIMK / 4; t += 32) {
            int row = t >> 4;          // 16 float4 per row
            int c4  = t & 15;
            uint32_t off = (uint32_t)(row * STR + c4 * 4) * 4u;
            cp16(xb + off, gx + t);
            cp16(yb + off, gy + t);
        }
    }
    cp_commit_wait();
    __syncwarp();

    float lsum = 0.f;

    if (valid) {
        const int a = lane >> 2;
        const int b = lane & 3;

        // hoist scalar global loads so their latency hides under the Gram loop
        const float wl0 = -wsc[g * MM + a]     * L2E_OVER_D;
        const float wl1 = -wsc[g * MM + a + 8] * L2E_OVER_D;
        const float twv = twg[g * MM];

        // ---- three 16x16 Gram matrices via packed f32x2 FMA ----
        // lane owns i in {a, a+8}, j in {b, b+4, b+8, b+12}
        unsigned long long Gxx[2][4], Gyy[2][4], Gxy[2][4];
#pragma unroll
        for (int p = 0; p < 2; p++)
#pragma unroll
            for (int c = 0; c < 4; c++) {
                Gxx[p][c] = 0ull; Gyy[p][c] = 0ull; Gxy[p][c] = 0ull;
            }

        const float* xa0p = X + a * STR;
        const float* xa1p = X + (a + 8) * STR;
        const float* ya0p = Y + a * STR;
        const float* ya1p = Y + (a + 8) * STR;

        // FULL unroll: no loop branch -> ptxas can software-pipeline LDS
        // batches across all 16 k-chunks instead of re-serializing every 4.
#pragma unroll
        for (int kk = 0; kk < DIMK / 4; kk++) {
            const int k = kk * 4;
            F4 xa0, xa1, ya0, ya1;
            xa0.v = *(const float4*)(xa0p + k);
            xa1.v = *(const float4*)(xa1p + k);
            ya0.v = *(const float4*)(ya0p + k);
            ya1.v = *(const float4*)(ya1p + k);
#pragma unroll
            for (int c = 0; c < 4; c++) {
                F4 xbv, ybv;
                xbv.v = *(const float4*)(X + (b + 4 * c) * STR + k);
                ybv.v = *(const float4*)(Y + (b + 4 * c) * STR + k);

                Gxx[0][c] = ffma2(xa0.u[0], xbv.u[0], Gxx[0][c]);
                Gxx[0][c] = ffma2(xa0.u[1], xbv.u[1], Gxx[0][c]);
                Gxx[1][c] = ffma2(xa1.u[0], xbv.u[0], Gxx[1][c]);
                Gxx[1][c] = ffma2(xa1.u[1], xbv.u[1], Gxx[1][c]);

                Gyy[0][c] = ffma2(ya0.u[0], ybv.u[0], Gyy[0][c]);
                Gyy[0][c] = ffma2(ya0.u[1], ybv.u[1], Gyy[0][c]);
                Gyy[1][c] = ffma2(ya1.u[0], ybv.u[0], Gyy[1][c]);
                Gyy[1][c] = ffma2(ya1.u[1], ybv.u[1], Gyy[1][c]);

                Gxy[0][c] = ffma2(xa0.u[0], ybv.u[0], Gxy[0][c]);
                Gxy[0][c] = ffma2(xa0.u[1], ybv.u[1], Gxy[0][c]);
                Gxy[1][c] = ffma2(xa1.u[0], ybv.u[0], Gxy[1][c]);
                Gxy[1][c] = ffma2(xa1.u[1], ybv.u[1], Gxy[1][c]);
            }
        }

        // ---- norms from the Gram diagonal (free): Gxx[i][i] = |x_i|^2 ----
        // Lane owns (i,i) iff b == (a&3): p=0 diag at c = a>>2, p=1 at c = (a>>2)+2.
        // Accumulation order identical to a dedicated norm pass -> bit-identical.
        if (b == (a & 3)) {
            const int hi = a >> 2;     // 0 or 1
            unsigned long long gx0 = hi ? Gxx[0][1] : Gxx[0][0];
            unsigned long long gy0 = hi ? Gyy[0][1] : Gyy[0][0];
            unsigned long long gx1 = hi ? Gxx[1][3] : Gxx[1][2];
            unsigned long long gy1 = hi ? Gyy[1][3] : Gyy[1][2];
            shn[warp][a]          = hsum2(gx0);
            shn[warp][16 + a]     = hsum2(gy0);
            shn[warp][a + 8]      = hsum2(gx1);
            shn[warp][16 + a + 8] = hsum2(gy1);
        }
        __syncwarp();

        // ---- epilogue: d^2 = n_i + n_j - 2 g_ij, clamp, MUFU sqrt + ex2 ----
        const float* nrm = shn[warp];
        const float nxa0 = nrm[a],      nxa1 = nrm[a + 8];
        const float nya0 = nrm[16 + a], nya1 = nrm[16 + a + 8];

#pragma unroll
        for (int c = 0; c < 4; c++) {
            const int j = b + 4 * c;
            const float nxj = nrm[j];
            const float nyj = nrm[16 + j];

            float d0 = fmaxf(fmaf(-2.f, hsum2(Gxx[0][c]), nxa0 + nxj), EPSV * EPSV);
            float d1 = fmaxf(fmaf(-2.f, hsum2(Gyy[0][c]), nya0 + nyj), EPSV * EPSV);
            float d2 = fmaxf(fmaf(-2.f, hsum2(Gxy[0][c]), nxa0 + nyj), EPSV * EPSV);
            float d3 = fmaxf(fmaf(-2.f, hsum2(Gxx[1][c]), nxa1 + nxj), EPSV * EPSV);
            float d4 = fmaxf(fmaf(-2.f, hsum2(Gyy[1][c]), nya1 + nyj), EPSV * EPSV);
            float d5 = fmaxf(fmaf(-2.f, hsum2(Gxy[1][c]), nxa1 + nyj), EPSV * EPSV);

            float t0 = mufu_ex2(wl0 * mufu_sqrt(d0));
            float t1 = mufu_ex2(wl0 * mufu_sqrt(d1));
            float t2 = mufu_ex2(wl0 * mufu_sqrt(d2));
            float t3 = mufu_ex2(wl1 * mufu_sqrt(d3));
            float t4 = mufu_ex2(wl1 * mufu_sqrt(d4));
            float t5 = mufu_ex2(wl1 * mufu_sqrt(d5));
            lsum += (t0 + t1 - 2.f * t2) + (t3 + t4 - 2.f * t5);
        }

        // warp reduction -> per-group value (deterministic)
#pragma unroll
        for (int off = 16; off; off >>= 1)
            lsum += __shfl_xor_sync(0xffffffffu, lsum, off);

        lsum *= twv * (1.0f / (float)(MM * MM));
    }

    if (lane == 0)
        s_part[warp] = valid ? lsum : 0.f;
    __syncthreads();

    // ---- block partial + last-block-done grid reduction ----
    if (threadIdx.x == 0) {
        float bs = 0.f;
#pragma unroll
        for (int w = 0; w < GPB; w++) bs += s_part[w];
        g_blocksum[blockIdx.x] = bs;
        __threadfence();
        unsigned int v = atomicAdd(&g_count, 1u);
        s_last = (v == gridDim.x - 1u) ? 1 : 0;
    }
    __syncthreads();

    if (s_last) {
        const int nb = gridDim.x;
        float acc = 0.f;
        for (int i = threadIdx.x; i < nb; i += GPB * 32)
            acc += g_blocksum[i];
#pragma unroll
        for (int off = 16; off; off >>= 1)
            acc += __shfl_xor_sync(0xffffffffu, acc, off);
        if (lane == 0) s_part[warp] = acc;
        __syncthreads();
        if (threadIdx.x == 0) {
            float tot = 0.f;
#pragma unroll
            for (int w = 0; w < GPB; w++) tot += s_part[w];
            out[0] = tot / (float)G;
            g_count = 0;   // reset for next graph replay
        }
    }
}

extern "C" void kernel_launch(void* const* d_in, const int* in_sizes, int n_in,
                              void* d_out, int out_size)
{
    const float* xs  = (const float*)d_in[0];   // ys_t
    const float* ysr = (const float*)d_in[1];   // ys_r_stop
    const float* ws  = (const float*)d_in[2];   // w_scale
    const float* tw  = (const float*)d_in[3];   // time_weights

    const int n = in_sizes[0];          // B * 16 * 4
    const int B = n / DIMK;
    int G = B / MM;
    if (G > MAXG) G = MAXG;

    const int blocks = (G + GPB - 1) / GPB;
    imm_fused_kernel<<<blocks, GPB * 32>>>(xs, ysr, ws, tw, (float*)d_out, G);
}